// round 1
// baseline (speedup 1.0000x reference)
#include <cuda_runtime.h>

#define SEQ   2048
#define DIM   1024
#define NB    4
#define MROWS (NB * SEQ)   // 8192

// ---------------- static device scratch (no allocations allowed) -------------
__device__ float g_q[MROWS * DIM];          // 32 MB
__device__ float g_k[MROWS * DIM];          // 32 MB
__device__ float g_v[MROWS * DIM];          // 32 MB
__device__ float g_att[(long long)NB * SEQ * SEQ]; // 64 MB

// ---------------- generic tiled fp32 GEMM ------------------------------------
// C[m,n] = sum_k A[m,k] * (TRANSB ? B[n,k] : B[k,n])  (+ bias[n])
// Tiles: BM=BN=64, BK=16, 256 threads, 4x4 per thread. All dims multiples of 64/16.
template <bool TRANSB>
__global__ __launch_bounds__(256)
void gemm64(const float* __restrict__ A, const float* __restrict__ B,
            const float* __restrict__ bias, float* __restrict__ C,
            int N, int K,
            long long sA, long long sB, long long sC)
{
    __shared__ float As[16][64];
    __shared__ float Bs[16][64];

    const float* Ab = A + (long long)blockIdx.z * sA;
    const float* Bb = B + (long long)blockIdx.z * sB;
    float*       Cb = C + (long long)blockIdx.z * sC;

    const int m0 = blockIdx.y * 64;
    const int n0 = blockIdx.x * 64;
    const int t  = threadIdx.x;
    const int ty = t >> 4;     // 0..15
    const int tx = t & 15;     // 0..15

    float acc[4][4] = {};

    for (int k0 = 0; k0 < K; k0 += 16) {
        // --- load A tile (64 rows x 16 k), transpose into As[k][m]
        {
            const int row = t >> 2;           // 0..63
            const int kc  = (t & 3) * 4;      // 0,4,8,12
            float4 a = *(const float4*)(Ab + (long long)(m0 + row) * K + k0 + kc);
            As[kc + 0][row] = a.x;
            As[kc + 1][row] = a.y;
            As[kc + 2][row] = a.z;
            As[kc + 3][row] = a.w;
        }
        // --- load B tile into Bs[k][n]
        if (TRANSB) {
            const int row = t >> 2;           // n index 0..63
            const int kc  = (t & 3) * 4;
            float4 b = *(const float4*)(Bb + (long long)(n0 + row) * K + k0 + kc);
            Bs[kc + 0][row] = b.x;
            Bs[kc + 1][row] = b.y;
            Bs[kc + 2][row] = b.z;
            Bs[kc + 3][row] = b.w;
        } else {
            const int kk = t >> 4;            // 0..15
            const int nc = (t & 15) * 4;      // 0..60
            *(float4*)&Bs[kk][nc] =
                *(const float4*)(Bb + (long long)(k0 + kk) * N + n0 + nc);
        }
        __syncthreads();

        #pragma unroll
        for (int kk = 0; kk < 16; kk++) {
            float4 a4 = *(const float4*)&As[kk][ty * 4];
            float4 b4 = *(const float4*)&Bs[kk][tx * 4];
            float av[4] = {a4.x, a4.y, a4.z, a4.w};
            float bvv[4] = {b4.x, b4.y, b4.z, b4.w};
            #pragma unroll
            for (int i = 0; i < 4; i++)
                #pragma unroll
                for (int j = 0; j < 4; j++)
                    acc[i][j] = fmaf(av[i], bvv[j], acc[i][j]);
        }
        __syncthreads();
    }

    #pragma unroll
    for (int i = 0; i < 4; i++) {
        const long long row = m0 + ty * 4 + i;
        #pragma unroll
        for (int j = 0; j < 4; j++) {
            const int col = n0 + tx * 4 + j;
            float val = acc[i][j];
            if (bias) val += bias[col];
            Cb[row * N + col] = val;
        }
    }
}

// ---------------- LayerNorm over rows of length DIM=1024 ---------------------
// One block (256 threads) per row; 4 elements per thread, two-pass mean/var.
__global__ __launch_bounds__(256)
void layernorm_k(float* __restrict__ Y,
                 const float* __restrict__ gamma,
                 const float* __restrict__ beta)
{
    __shared__ float red[8];
    const long long row = blockIdx.x;
    float* y = Y + row * DIM;
    const int t = threadIdx.x;
    const int lane = t & 31, warp = t >> 5;

    float4 v = *(const float4*)(y + t * 4);

    // mean
    float s = v.x + v.y + v.z + v.w;
    #pragma unroll
    for (int o = 16; o > 0; o >>= 1) s += __shfl_xor_sync(0xffffffffu, s, o);
    if (lane == 0) red[warp] = s;
    __syncthreads();
    if (t == 0) {
        float m = 0.f;
        #pragma unroll
        for (int i = 0; i < 8; i++) m += red[i];
        red[0] = m;
    }
    __syncthreads();
    const float mu = red[0] * (1.0f / DIM);
    __syncthreads();   // everyone has read red[0] before reuse

    // variance (two-pass, matches reference)
    float dx = v.x - mu, dy = v.y - mu, dz = v.z - mu, dw = v.w - mu;
    float sq = dx * dx + dy * dy + dz * dz + dw * dw;
    #pragma unroll
    for (int o = 16; o > 0; o >>= 1) sq += __shfl_xor_sync(0xffffffffu, sq, o);
    if (lane == 0) red[warp] = sq;
    __syncthreads();
    if (t == 0) {
        float m = 0.f;
        #pragma unroll
        for (int i = 0; i < 8; i++) m += red[i];
        red[0] = m;
    }
    __syncthreads();
    const float var = red[0] * (1.0f / DIM);
    const float rs  = rsqrtf(var + 1e-5f);

    const int c = t * 4;
    float4 o;
    o.x = dx * rs * gamma[c + 0] + beta[c + 0];
    o.y = dy * rs * gamma[c + 1] + beta[c + 1];
    o.z = dz * rs * gamma[c + 2] + beta[c + 2];
    o.w = dw * rs * gamma[c + 3] + beta[c + 3];
    *(float4*)(y + c) = o;
}

// ---------------- row softmax over length SEQ=2048 ---------------------------
// One block (256 threads) per row; 8 elements per thread.
__global__ __launch_bounds__(256)
void softmax_k(float* __restrict__ Att)
{
    __shared__ float red[8];
    const long long row = blockIdx.x;
    float* a = Att + row * (long long)SEQ;
    const int t = threadIdx.x;
    const int lane = t & 31, warp = t >> 5;

    float v[8];
    float mx = -3.402823e38f;
    #pragma unroll
    for (int i = 0; i < 8; i++) {
        v[i] = a[t + i * 256];
        mx = fmaxf(mx, v[i]);
    }
    #pragma unroll
    for (int o = 16; o > 0; o >>= 1) mx = fmaxf(mx, __shfl_xor_sync(0xffffffffu, mx, o));
    if (lane == 0) red[warp] = mx;
    __syncthreads();
    if (t == 0) {
        float m = red[0];
        #pragma unroll
        for (int i = 1; i < 8; i++) m = fmaxf(m, red[i]);
        red[0] = m;
    }
    __syncthreads();
    mx = red[0];
    __syncthreads();   // all read red[0] before reuse

    float sum = 0.f;
    #pragma unroll
    for (int i = 0; i < 8; i++) {
        v[i] = __expf(v[i] - mx);
        sum += v[i];
    }
    #pragma unroll
    for (int o = 16; o > 0; o >>= 1) sum += __shfl_xor_sync(0xffffffffu, sum, o);
    if (lane == 0) red[warp] = sum;
    __syncthreads();
    if (t == 0) {
        float m = 0.f;
        #pragma unroll
        for (int i = 0; i < 8; i++) m += red[i];
        red[0] = m;
    }
    __syncthreads();
    const float inv = 1.0f / red[0];

    #pragma unroll
    for (int i = 0; i < 8; i++) a[t + i * 256] = v[i] * inv;
}

// ---------------- launch ------------------------------------------------------
extern "C" void kernel_launch(void* const* d_in, const int* in_sizes, int n_in,
                              void* d_out, int out_size)
{
    const float* x     = (const float*)d_in[0];
    const float* Wq    = (const float*)d_in[1];
    const float* bq    = (const float*)d_in[2];
    const float* Wk    = (const float*)d_in[3];
    const float* bk    = (const float*)d_in[4];
    const float* Wv    = (const float*)d_in[5];
    const float* bv    = (const float*)d_in[6];
    const float* gamma = (const float*)d_in[7];
    const float* beta  = (const float*)d_in[8];
    float* out = (float*)d_out;

    float *q, *k, *v, *att;
    cudaGetSymbolAddress((void**)&q,   g_q);
    cudaGetSymbolAddress((void**)&k,   g_k);
    cudaGetSymbolAddress((void**)&v,   g_v);
    cudaGetSymbolAddress((void**)&att, g_att);

    // 1) projections: y = x @ W^T + b   (M=8192, N=1024, K=1024)
    dim3 gProj(DIM / 64, MROWS / 64, 1);
    gemm64<true><<<gProj, 256>>>(x, Wq, bq, q, DIM, DIM, 0, 0, 0);
    gemm64<true><<<gProj, 256>>>(x, Wk, bk, k, DIM, DIM, 0, 0, 0);
    gemm64<true><<<gProj, 256>>>(x, Wv, bv, v, DIM, DIM, 0, 0, 0);

    // 2) LayerNorm each row
    layernorm_k<<<MROWS, 256>>>(q, gamma, beta);
    layernorm_k<<<MROWS, 256>>>(k, gamma, beta);
    layernorm_k<<<MROWS, 256>>>(v, gamma, beta);

    // 3) scores = q @ k^T per batch (M=N=2048, K=1024)
    dim3 gScore(SEQ / 64, SEQ / 64, NB);
    gemm64<true><<<gScore, 256>>>(q, k, nullptr, att, SEQ, DIM,
                                  (long long)SEQ * DIM, (long long)SEQ * DIM,
                                  (long long)SEQ * SEQ);

    // 4) row softmax
    softmax_k<<<NB * SEQ, 256>>>(att);

    // 5) out = att @ v per batch (M=2048, N=1024, K=2048)
    dim3 gOut(DIM / 64, SEQ / 64, NB);
    gemm64<false><<<gOut, 256>>>(att, v, nullptr, out, DIM, SEQ,
                                 (long long)SEQ * SEQ, (long long)SEQ * DIM,
                                 (long long)SEQ * DIM);
}

// round 3
// speedup vs baseline: 1.9838x; 1.9838x over previous
#include <cuda_runtime.h>
#include <cuda_fp16.h>
#include <cstdint>

#define SEQ  2048
#define DIM  1024
#define NBAT 4
#define MROWS (NBAT * SEQ)   // 8192
#define BK   32

// ----------------------- static device scratch -------------------------------
__device__ __half g_xh[MROWS * DIM], g_xl[MROWS * DIM];
__device__ __half g_wh[3 * DIM * DIM], g_wl[3 * DIM * DIM];
__device__ float  g_y[(size_t)MROWS * 3 * DIM];                 // 96MB
__device__ __half g_qh[MROWS * DIM], g_ql[MROWS * DIM];
__device__ __half g_kh[MROWS * DIM], g_kl[MROWS * DIM];
__device__ __half g_vh[MROWS * DIM], g_vl[MROWS * DIM];
__device__ __half g_vhT[MROWS * DIM], g_vlT[MROWS * DIM];
__device__ float  g_att[(size_t)NBAT * SEQ * SEQ];              // 64MB
__device__ __half g_ah[(size_t)NBAT * SEQ * SEQ];
__device__ __half g_al[(size_t)NBAT * SEQ * SEQ];

// ----------------------- PTX helpers -----------------------------------------
__device__ __forceinline__ uint32_t s2u(const void* p) {
    uint32_t a;
    asm("{ .reg .u64 t; cvta.to.shared.u64 t, %1; cvt.u32.u64 %0, t; }" : "=r"(a) : "l"(p));
    return a;
}
__device__ __forceinline__ void cp16(uint32_t dst, const void* src) {
    asm volatile("cp.async.cg.shared.global [%0], [%1], 16;" :: "r"(dst), "l"(src));
}
__device__ __forceinline__ void cp_commit() { asm volatile("cp.async.commit_group;" ::: "memory"); }
template <int N>
__device__ __forceinline__ void cp_wait() { asm volatile("cp.async.wait_group %0;" :: "n"(N) : "memory"); }

__device__ __forceinline__ void ldsm4(uint32_t& d0, uint32_t& d1, uint32_t& d2, uint32_t& d3,
                                      uint32_t addr) {
    asm volatile("ldmatrix.sync.aligned.m8n8.x4.shared.b16 {%0,%1,%2,%3}, [%4];"
                 : "=r"(d0), "=r"(d1), "=r"(d2), "=r"(d3) : "r"(addr));
}
__device__ __forceinline__ void ldsm2(uint32_t& d0, uint32_t& d1, uint32_t addr) {
    asm volatile("ldmatrix.sync.aligned.m8n8.x2.shared.b16 {%0,%1}, [%2];"
                 : "=r"(d0), "=r"(d1) : "r"(addr));
}
__device__ __forceinline__ void mma16816(float* d, const uint32_t* a, const uint32_t* b) {
    asm volatile("mma.sync.aligned.m16n8k16.row.col.f32.f16.f16.f32 "
                 "{%0,%1,%2,%3}, {%4,%5,%6,%7}, {%8,%9}, {%0,%1,%2,%3};"
                 : "+f"(d[0]), "+f"(d[1]), "+f"(d[2]), "+f"(d[3])
                 : "r"(a[0]), "r"(a[1]), "r"(a[2]), "r"(a[3]), "r"(b[0]), "r"(b[1]));
}

// ----------------------- HMMA split-fp16 GEMM ---------------------------------
// C[M,N](f32) = Ah@Bh^T + Ah@Bl^T + Al@Bh^T (+bias). A:[M,K], B:[N,K], K-major fp16.
// Tile 128x128xBK32, 256 threads, warp grid 2x4, warp tile 64x32.
template <bool HAS_BIAS>
__global__ __launch_bounds__(256, 2)
void gemm_hmma(const __half* __restrict__ Ah, const __half* __restrict__ Al,
               const __half* __restrict__ Bh, const __half* __restrict__ Bl,
               const float* __restrict__ bias0, const float* __restrict__ bias1,
               const float* __restrict__ bias2,
               float* __restrict__ C, int N, int K,
               long long sA, long long sB, long long sC)
{
    __shared__ __align__(128) unsigned char smem[2 * 16384];   // 2 stages x (A 8KB + B 8KB)
    const int t = threadIdx.x, lane = t & 31, wid = t >> 5;
    const int wr = wid >> 2, wc = wid & 3;
    const int m0 = blockIdx.y * 128, n0 = blockIdx.x * 128;
    const int z = blockIdx.z;
    Ah += (size_t)z * sA;  Al += (size_t)z * sA;
    Bh += (size_t)z * sB;  Bl += (size_t)z * sB;
    C  += (size_t)z * sC;
    const uint32_t sb = s2u(smem);

    const int kc = K / BK;
    const int nc = 3 * kc;

    float acc[4][4][4];
    #pragma unroll
    for (int i = 0; i < 4; i++)
        #pragma unroll
        for (int j = 0; j < 4; j++)
            #pragma unroll
            for (int r = 0; r < 4; r++) acc[i][j][r] = 0.f;

    auto loadc = [&](int c, int st) {
        const int term = c / kc;
        const int k0   = (c - term * kc) * BK;
        const __half* As = (term == 2) ? Al : Ah;
        const __half* Bs = (term == 1) ? Bl : Bh;
        const uint32_t ab = sb + st * 16384;
        const uint32_t bb = ab + 8192;
        const int row = t >> 1;
        const int c2  = (t & 1) * 2;
        #pragma unroll
        for (int j = 0; j < 2; j++) {
            const int cc = c2 + j;
            const uint32_t sw = (uint32_t)((cc ^ (row & 3)) << 4);
            cp16(ab + row * 64 + sw, As + (size_t)(m0 + row) * K + k0 + cc * 8);
            cp16(bb + row * 64 + sw, Bs + (size_t)(n0 + row) * K + k0 + cc * 8);
        }
        cp_commit();
    };

    loadc(0, 0);

    for (int c = 0; c < nc; c++) {
        const int cur = c & 1;
        if (c + 1 < nc) {
            loadc(c + 1, cur ^ 1);
            cp_wait<1>();
        } else {
            cp_wait<0>();
        }
        __syncthreads();

        const uint32_t ab = sb + cur * 16384;
        const uint32_t bb = ab + 8192;

        #pragma unroll
        for (int ks = 0; ks < 2; ks++) {
            uint32_t a[4][4], b[4][2];
            #pragma unroll
            for (int mt = 0; mt < 4; mt++) {
                const int r  = wr * 64 + mt * 16 + (lane & 15);
                const int k8 = ks * 2 + (lane >> 4);
                ldsm4(a[mt][0], a[mt][1], a[mt][2], a[mt][3],
                      ab + r * 64 + ((k8 ^ (r & 3)) << 4));
            }
            #pragma unroll
            for (int nt = 0; nt < 4; nt++) {
                const int r  = wc * 32 + nt * 8 + (lane & 7);
                const int k8 = ks * 2 + ((lane >> 3) & 1);
                ldsm2(b[nt][0], b[nt][1],
                      bb + r * 64 + ((k8 ^ (r & 3)) << 4));
            }
            #pragma unroll
            for (int mt = 0; mt < 4; mt++)
                #pragma unroll
                for (int nt = 0; nt < 4; nt++)
                    mma16816(acc[mt][nt], a[mt], b[nt]);
        }
        __syncthreads();
    }

    // epilogue: acc -> gmem (float2 per fragment row), fused bias
    const int third = HAS_BIAS ? (n0 / DIM) : 0;
    const float* bp = (third == 0) ? bias0 : (third == 1) ? bias1 : bias2;
    const int bcol0 = n0 - third * DIM;

    #pragma unroll
    for (int mt = 0; mt < 4; mt++) {
        const int row = m0 + wr * 64 + mt * 16 + (lane >> 2);
        #pragma unroll
        for (int nt = 0; nt < 4; nt++) {
            const int cofs = wc * 32 + nt * 8 + (lane & 3) * 2;
            const int col  = n0 + cofs;
            float2 v0 = make_float2(acc[mt][nt][0], acc[mt][nt][1]);
            float2 v1 = make_float2(acc[mt][nt][2], acc[mt][nt][3]);
            if (HAS_BIAS) {
                float2 bb2 = *(const float2*)(bp + bcol0 + cofs);
                v0.x += bb2.x; v0.y += bb2.y;
                v1.x += bb2.x; v1.y += bb2.y;
            }
            *(float2*)(C + (size_t)row * N + col)       = v0;
            *(float2*)(C + (size_t)(row + 8) * N + col) = v1;
        }
    }
}

// ----------------------- split f32 -> (hi, lo) fp16 ---------------------------
__global__ __launch_bounds__(256)
void split_k(const float* __restrict__ x, __half* __restrict__ H,
             __half* __restrict__ L, int n4)
{
    int i = blockIdx.x * blockDim.x + threadIdx.x;
    if (i >= n4) return;
    float4 v = ((const float4*)x)[i];
    __half h0 = __float2half(v.x), h1 = __float2half(v.y);
    __half h2 = __float2half(v.z), h3 = __float2half(v.w);
    __half l0 = __float2half(v.x - __half2float(h0));
    __half l1 = __float2half(v.y - __half2float(h1));
    __half l2 = __float2half(v.z - __half2float(h2));
    __half l3 = __float2half(v.w - __half2float(h3));
    ((__half2*)H)[i * 2 + 0] = __halves2half2(h0, h1);
    ((__half2*)H)[i * 2 + 1] = __halves2half2(h2, h3);
    ((__half2*)L)[i * 2 + 0] = __halves2half2(l0, l1);
    ((__half2*)L)[i * 2 + 1] = __halves2half2(l2, l3);
}

// ----------------------- LayerNorm + split ------------------------------------
__global__ __launch_bounds__(256)
void ln_split_k(const float* __restrict__ Y, int ldy,
                const float* __restrict__ gamma, const float* __restrict__ beta,
                __half* __restrict__ H, __half* __restrict__ L)
{
    __shared__ float red[8];
    const size_t row = blockIdx.x;
    const float* y = Y + row * ldy;
    const int t = threadIdx.x, lane = t & 31, warp = t >> 5;

    float4 v = *(const float4*)(y + t * 4);
    float s = v.x + v.y + v.z + v.w;
    #pragma unroll
    for (int o = 16; o > 0; o >>= 1) s += __shfl_xor_sync(0xffffffffu, s, o);
    if (lane == 0) red[warp] = s;
    __syncthreads();
    if (t == 0) { float m = 0.f; for (int i = 0; i < 8; i++) m += red[i]; red[0] = m; }
    __syncthreads();
    const float mu = red[0] * (1.0f / DIM);
    __syncthreads();

    float dx = v.x - mu, dy = v.y - mu, dz = v.z - mu, dw = v.w - mu;
    float sq = dx * dx + dy * dy + dz * dz + dw * dw;
    #pragma unroll
    for (int o = 16; o > 0; o >>= 1) sq += __shfl_xor_sync(0xffffffffu, sq, o);
    if (lane == 0) red[warp] = sq;
    __syncthreads();
    if (t == 0) { float m = 0.f; for (int i = 0; i < 8; i++) m += red[i]; red[0] = m; }
    __syncthreads();
    const float rs = rsqrtf(red[0] * (1.0f / DIM) + 1e-5f);

    const int c = t * 4;
    float o0 = dx * rs * gamma[c + 0] + beta[c + 0];
    float o1 = dy * rs * gamma[c + 1] + beta[c + 1];
    float o2 = dz * rs * gamma[c + 2] + beta[c + 2];
    float o3 = dw * rs * gamma[c + 3] + beta[c + 3];

    __half h0 = __float2half(o0), h1 = __float2half(o1);
    __half h2 = __float2half(o2), h3 = __float2half(o3);
    __half l0 = __float2half(o0 - __half2float(h0));
    __half l1 = __float2half(o1 - __half2float(h1));
    __half l2 = __float2half(o2 - __half2float(h2));
    __half l3 = __float2half(o3 - __half2float(h3));
    *(__half2*)(H + row * DIM + c + 0) = __halves2half2(h0, h1);
    *(__half2*)(H + row * DIM + c + 2) = __halves2half2(h2, h3);
    *(__half2*)(L + row * DIM + c + 0) = __halves2half2(l0, l1);
    *(__half2*)(L + row * DIM + c + 2) = __halves2half2(l2, l3);
}

// ----------------------- fp16 transpose (per batch) ---------------------------
__global__ __launch_bounds__(256)
void transpose_h(const __half* __restrict__ in, __half* __restrict__ out)
{
    __shared__ __half tile[32][36];
    const int b = blockIdx.z;
    in  += (size_t)b * SEQ * DIM;
    out += (size_t)b * DIM * SEQ;
    const int r0 = blockIdx.y * 32;   // token rows
    const int c0 = blockIdx.x * 32;   // dim cols
    const int t = threadIdx.x;
    const int lr = t >> 3, lc = (t & 7) * 4;

    *(uint2*)&tile[lr][lc] = *(const uint2*)(in + (size_t)(r0 + lr) * DIM + c0 + lc);
    __syncthreads();

    const int oc = t >> 3, orr = (t & 7) * 4;
    uint2 w;
    w.x = (uint32_t)__half_as_ushort(tile[orr + 0][oc]) |
          ((uint32_t)__half_as_ushort(tile[orr + 1][oc]) << 16);
    w.y = (uint32_t)__half_as_ushort(tile[orr + 2][oc]) |
          ((uint32_t)__half_as_ushort(tile[orr + 3][oc]) << 16);
    *(uint2*)(out + (size_t)(c0 + oc) * SEQ + r0 + orr) = w;
}

// ----------------------- softmax + split --------------------------------------
__global__ __launch_bounds__(256)
void softmax_split_k(const float* __restrict__ Att,
                     __half* __restrict__ H, __half* __restrict__ L)
{
    __shared__ float red[8];
    const size_t row = blockIdx.x;
    const float* a = Att + row * (size_t)SEQ;
    const int t = threadIdx.x, lane = t & 31, warp = t >> 5;

    float v[8];
    float mx = -3.402823e38f;
    #pragma unroll
    for (int i = 0; i < 8; i++) { v[i] = a[t + i * 256]; mx = fmaxf(mx, v[i]); }
    #pragma unroll
    for (int o = 16; o > 0; o >>= 1) mx = fmaxf(mx, __shfl_xor_sync(0xffffffffu, mx, o));
    if (lane == 0) red[warp] = mx;
    __syncthreads();
    if (t == 0) { float m = red[0]; for (int i = 1; i < 8; i++) m = fmaxf(m, red[i]); red[0] = m; }
    __syncthreads();
    mx = red[0];
    __syncthreads();

    float sum = 0.f;
    #pragma unroll
    for (int i = 0; i < 8; i++) { v[i] = __expf(v[i] - mx); sum += v[i]; }
    #pragma unroll
    for (int o = 16; o > 0; o >>= 1) sum += __shfl_xor_sync(0xffffffffu, sum, o);
    if (lane == 0) red[warp] = sum;
    __syncthreads();
    if (t == 0) { float m = 0.f; for (int i = 0; i < 8; i++) m += red[i]; red[0] = m; }
    __syncthreads();
    const float inv = 1.0f / red[0];

    #pragma unroll
    for (int i = 0; i < 8; i++) {
        float w = v[i] * inv;
        __half h = __float2half(w);
        __half l = __float2half(w - __half2float(h));
        H[row * (size_t)SEQ + t + i * 256] = h;
        L[row * (size_t)SEQ + t + i * 256] = l;
    }
}

// ----------------------- launch ------------------------------------------------
extern "C" void kernel_launch(void* const* d_in, const int* in_sizes, int n_in,
                              void* d_out, int out_size)
{
    const float* x      = (const float*)d_in[0];
    const float* W[3]   = {(const float*)d_in[1], (const float*)d_in[3], (const float*)d_in[5]};
    const float* bias[3]= {(const float*)d_in[2], (const float*)d_in[4], (const float*)d_in[6]};
    const float* gamma  = (const float*)d_in[7];
    const float* beta   = (const float*)d_in[8];
    float* out = (float*)d_out;

    __half *xh, *xl, *wh, *wl, *qh, *ql, *kh, *kl, *vh, *vl, *vhT, *vlT, *ah, *al;
    float *y, *att;
    cudaGetSymbolAddress((void**)&xh, g_xh);   cudaGetSymbolAddress((void**)&xl, g_xl);
    cudaGetSymbolAddress((void**)&wh, g_wh);   cudaGetSymbolAddress((void**)&wl, g_wl);
    cudaGetSymbolAddress((void**)&y,  g_y);
    cudaGetSymbolAddress((void**)&qh, g_qh);   cudaGetSymbolAddress((void**)&ql, g_ql);
    cudaGetSymbolAddress((void**)&kh, g_kh);   cudaGetSymbolAddress((void**)&kl, g_kl);
    cudaGetSymbolAddress((void**)&vh, g_vh);   cudaGetSymbolAddress((void**)&vl, g_vl);
    cudaGetSymbolAddress((void**)&vhT, g_vhT); cudaGetSymbolAddress((void**)&vlT, g_vlT);
    cudaGetSymbolAddress((void**)&att, g_att);
    cudaGetSymbolAddress((void**)&ah, g_ah);   cudaGetSymbolAddress((void**)&al, g_al);

    // 1) split x and the 3 weights (weights concatenated: [3072, 1024] K-major)
    {
        int n4 = MROWS * DIM / 4;
        split_k<<<(n4 + 255) / 256, 256>>>(x, xh, xl, n4);
        int w4 = DIM * DIM / 4;
        for (int i = 0; i < 3; i++)
            split_k<<<(w4 + 255) / 256, 256>>>(W[i], wh + (size_t)i * DIM * DIM,
                                               wl + (size_t)i * DIM * DIM, w4);
    }

    // 2) fused QKV projection: [8192, 3072] = x @ Wqkv^T + bias
    dim3 gProj(3 * DIM / 128, MROWS / 128, 1);
    gemm_hmma<true><<<gProj, 256>>>(xh, xl, wh, wl, bias[0], bias[1], bias[2],
                                    y, 3 * DIM, DIM, 0, 0, 0);

    // 3) LayerNorm + split per projection
    __half* outsH[3] = {qh, kh, vh};
    __half* outsL[3] = {ql, kl, vl};
    for (int i = 0; i < 3; i++)
        ln_split_k<<<MROWS, 256>>>(y + (size_t)i * DIM, 3 * DIM, gamma, beta,
                                   outsH[i], outsL[i]);

    // 4) transpose v for att@v
    dim3 gT(DIM / 32, SEQ / 32, NBAT);
    transpose_h<<<gT, 256>>>(vh, vhT);
    transpose_h<<<gT, 256>>>(vl, vlT);

    // 5) scores = q @ k^T (per batch)
    dim3 gScore(SEQ / 128, SEQ / 128, NBAT);
    gemm_hmma<false><<<gScore, 256>>>(qh, ql, kh, kl, nullptr, nullptr, nullptr,
                                      att, SEQ, DIM,
                                      (long long)SEQ * DIM, (long long)SEQ * DIM,
                                      (long long)SEQ * SEQ);

    // 6) softmax + split
    softmax_split_k<<<NBAT * SEQ, 256>>>(att, ah, al);

    // 7) out = att @ v (B = v^T, [DIM, SEQ] K-major per batch)
    dim3 gOut(DIM / 128, SEQ / 128, NBAT);
    gemm_hmma<false><<<gOut, 256>>>(ah, al, vhT, vlT, nullptr, nullptr, nullptr,
                                    out, DIM, SEQ,
                                    (long long)SEQ * SEQ, (long long)DIM * SEQ,
                                    (long long)SEQ * DIM);
}